// round 17
// baseline (speedup 1.0000x reference)
#include <cuda_runtime.h>
#include <cuda_fp16.h>
#include <cstdint>

#define N_R 40000
#define N_U 30000
#define N_P 30000
#define NN  100000
#define EE  1600000
#define F   128
#define C   40
#define ZC  21            // logical stacked width
#define ZS  40            // z row stride in halves (80B)
#define TN  128           // nodes per MLP block
#define C2P 32            // h2 row stride in half2 units (128B -> 1 L1 line per row)
#define PHP 16            // P row stride in half2 units (64B -> never crosses a line)
#define CAP 64            // bucket capacity (max degree; Poisson(16) -> P(>64) ~ 1e-18)

#define PB_BLOCKS   391   // ceil(NN / 256)
#define WSF_BLOCKS  4     // 1024 fragment threads
#define W2F_BLOCKS  5     // 1280 fragment threads
#define SC_BLOCKS   1563  // ceil(EE/4 / 256)

// ---------------- device scratch (static, no allocation) ----------------
__device__ __half2 g_Ph[(size_t)(NN + 16) * PHP];    // fp16 padded per-node raw features
__device__ __half  g_zh[(size_t)(NN + 128) * ZS];    // aggregated feats (fp16)
__device__ __half2 g_h2h[(size_t)(NN + 16) * C2P];   // h2, 128B stride
__device__ uint2   g_Wsf[16 * 2 * 32];               // Ws fragments: [nt][kt][lane] -> (b0,b1)
__device__ uint2   g_W2f[8 * 5 * 32];                // W2 fragments: [kt][nt][lane] -> (b0,b1)
__device__ int     g_deg[NN];                        // invariant: zero at entry (agg2 resets)
__device__ int     g_srcs[(size_t)NN * CAP];         // bucketed adjacency

// fused layer-1 weight element: Ws[k][col] = stacked[k] . W1[:,col]
__device__ __forceinline__ float fused_ws(int k, int col,
    const float* Wr, const float* br, const float* Wu, const float* bu,
    const float* Wp, const float* bp, const float* W1)
{
    if (k >= ZC) return 0.f;
    const float* v;
    if (k < 5)        v = Wr + k * F;
    else if (k < 12)  v = Wu + (k - 5) * F;
    else if (k < 18)  v = Wp + (k - 12) * F;
    else if (k == 18) v = br;
    else if (k == 19) v = bu;
    else              v = bp;
    float acc = 0.f;
    for (int j = 0; j < F; j++) acc += v[j] * W1[j * F + col];
    return acc;
}

// ---- blocks [0,391): P(fp16); [391,395): Ws frags; [395,400): W2 frags; [400,1963): scatter ----
__global__ void k_prepscatter(
    const float* __restrict__ Wr, const float* __restrict__ br,
    const float* __restrict__ Wu, const float* __restrict__ bu,
    const float* __restrict__ Wp, const float* __restrict__ bp,
    const float* __restrict__ W1, const float* __restrict__ W2,
    const float* __restrict__ xr, const float* __restrict__ xu,
    const float* __restrict__ xp,
    const int* __restrict__ src, const int* __restrict__ dst)
{
    if (blockIdx.x < PB_BLOCKS) {
        int n = blockIdx.x * 256 + threadIdx.x;
        if (n < NN) {
            float p[24];
            #pragma unroll
            for (int k = 0; k < 24; k++) p[k] = 0.f;
            if (n < N_R) {
                #pragma unroll
                for (int k = 0; k < 5; k++) p[k] = xr[(size_t)n * 5 + k];
                p[18] = 1.f;
            } else if (n < N_R + N_U) {
                int m = n - N_R;
                #pragma unroll
                for (int k = 0; k < 7; k++) p[5 + k] = xu[(size_t)m * 7 + k];
                p[19] = 1.f;
            } else {
                int m = n - N_R - N_U;
                #pragma unroll
                for (int k = 0; k < 6; k++) p[12 + k] = xp[(size_t)m * 6 + k];
                p[20] = 1.f;
            }
            __half2 hb[12];
            #pragma unroll
            for (int q = 0; q < 12; q++)
                hb[q] = __floats2half2_rn(p[2 * q], p[2 * q + 1]);
            uint4* d = (uint4*)&g_Ph[(size_t)n * PHP];
            d[0] = *(uint4*)&hb[0];
            d[1] = *(uint4*)&hb[4];
            d[2] = *(uint4*)&hb[8];
        }
    } else if (blockIdx.x < PB_BLOCKS + WSF_BLOCKS) {
        int idx = (blockIdx.x - PB_BLOCKS) * 256 + threadIdx.x;
        if (idx < 16 * 2 * 32) {
            int lane = idx & 31, t = idx >> 5;
            int kt = t & 1, nt = t >> 1;
            int g = lane >> 2, q = lane & 3;
            int col = 8 * nt + g;
            int k0  = kt * 16 + 2 * q;
            float h0 = fused_ws(k0,     col, Wr, br, Wu, bu, Wp, bp, W1);
            float h1 = fused_ws(k0 + 1, col, Wr, br, Wu, bu, Wp, bp, W1);
            float h2 = fused_ws(k0 + 8, col, Wr, br, Wu, bu, Wp, bp, W1);
            float h3 = fused_ws(k0 + 9, col, Wr, br, Wu, bu, Wp, bp, W1);
            __half2 b0 = __floats2half2_rn(h0, h1);
            __half2 b1 = __floats2half2_rn(h2, h3);
            g_Wsf[idx] = make_uint2(*(uint32_t*)&b0, *(uint32_t*)&b1);
        }
    } else if (blockIdx.x < PB_BLOCKS + WSF_BLOCKS + W2F_BLOCKS) {
        int idx = (blockIdx.x - PB_BLOCKS - WSF_BLOCKS) * 256 + threadIdx.x;
        if (idx < 8 * 5 * 32) {
            int lane = idx & 31, t = idx >> 5;
            int nt = t % 5, kt = t / 5;
            int g = lane >> 2, q = lane & 3;
            int col = 8 * nt + g;
            int k0  = kt * 16 + 2 * q;
            __half2 b0 = __floats2half2_rn(W2[k0 * C + col],       W2[(k0 + 1) * C + col]);
            __half2 b1 = __floats2half2_rn(W2[(k0 + 8) * C + col], W2[(k0 + 9) * C + col]);
            g_W2f[idx] = make_uint2(*(uint32_t*)&b0, *(uint32_t*)&b1);
        }
    } else {
        int t = (blockIdx.x - PB_BLOCKS - WSF_BLOCKS - W2F_BLOCKS) * 256 + threadIdx.x;
        if (t < EE / 4) {
            int4 d4 = ((const int4*)dst)[t];
            int4 s4 = ((const int4*)src)[t];
            int p0 = atomicAdd(&g_deg[d4.x], 1);
            int p1 = atomicAdd(&g_deg[d4.y], 1);
            int p2 = atomicAdd(&g_deg[d4.z], 1);
            int p3 = atomicAdd(&g_deg[d4.w], 1);
            if (p0 < CAP) g_srcs[(size_t)d4.x * CAP + p0] = s4.x;
            if (p1 < CAP) g_srcs[(size_t)d4.y * CAP + p1] = s4.y;
            if (p2 < CAP) g_srcs[(size_t)d4.z * CAP + p2] = s4.z;
            if (p3 < CAP) g_srcs[(size_t)d4.w * CAP + p3] = s4.w;
        }
    }
}

// ---------------- layer-1 aggregate: 4 lanes/node (3 active), pairwise HADD2 ----------------
__global__ void k_aggz()
{
    int gid  = blockIdx.x * blockDim.x + threadIdx.x;
    int node = gid >> 2;
    if (node >= NN) return;
    int lane = gid & 3;
    if (lane >= 3) return;            // 3 active lanes x 16B = 48B row (1 line, 64B stride)
    int deg = g_deg[node];
    if (deg > CAP) deg = CAP;
    const int* srcs = g_srcs + (size_t)node * CAP;
    const uint4* ph4 = (const uint4*)g_Ph;     // row stride = 4 uint4
    float a[8];
    #pragma unroll
    for (int i = 0; i < 8; i++) a[i] = 0.f;
    int j = 0;
    for (; j + 3 < deg; j += 4) {
        uint4 q0 = ph4[(size_t)srcs[j]     * 4 + lane];
        uint4 q1 = ph4[(size_t)srcs[j + 1] * 4 + lane];
        uint4 q2 = ph4[(size_t)srcs[j + 2] * 4 + lane];
        uint4 q3 = ph4[(size_t)srcs[j + 3] * 4 + lane];
        const __half2* h0 = (const __half2*)&q0;
        const __half2* h1 = (const __half2*)&q1;
        const __half2* h2 = (const __half2*)&q2;
        const __half2* h3 = (const __half2*)&q3;
        #pragma unroll
        for (int i = 0; i < 4; i++) {
            float2 s = __half22float2(__hadd2(h0[i], h1[i]));
            float2 u = __half22float2(__hadd2(h2[i], h3[i]));
            a[2 * i]     += s.x + u.x;
            a[2 * i + 1] += s.y + u.y;
        }
    }
    for (; j < deg; j++) {
        uint4 q = ph4[(size_t)srcs[j] * 4 + lane];
        const __half2* h = (const __half2*)&q;
        #pragma unroll
        for (int i = 0; i < 4; i++) {
            float2 f = __half22float2(h[i]);
            a[2 * i]     += f.x;
            a[2 * i + 1] += f.y;
        }
    }
    __half2 hb[4];
    #pragma unroll
    for (int i = 0; i < 4; i++)
        hb[i] = __floats2half2_rn(a[2 * i], a[2 * i + 1]);
    *(uint4*)&g_zh[(size_t)node * ZS + 8 * lane] = *(uint4*)&hb[0];
}

// ---------------- 2-layer MLP: all-HMMA, interleaved phases, no smem ----------------
__global__ void __launch_bounds__(256)
k_mlp()
{
    int tid  = threadIdx.x;           // 0..255
    int w    = tid >> 5;              // warp 0..7 -> node rows [16w, 16w+16)
    int lane = tid & 31;
    int g    = lane >> 2;             // 0..7
    int q    = lane & 3;              // 0..3
    int nodeBase = blockIdx.x * TN;
    int r0 = nodeBase + w * 16 + g;   // global node row (g_zh padded: +128 rows)

    // A-fragments of z straight from gmem (L2-resident)
    uint32_t a[2][4];
    #pragma unroll
    for (int zk = 0; zk < 2; zk++) {
        int kb = zk * 16 + 2 * q;
        a[zk][0] = *(const uint32_t*)&g_zh[(size_t)r0 * ZS + kb];
        a[zk][1] = *(const uint32_t*)&g_zh[(size_t)(r0 + 8) * ZS + kb];
        a[zk][2] = *(const uint32_t*)&g_zh[(size_t)r0 * ZS + kb + 8];
        a[zk][3] = *(const uint32_t*)&g_zh[(size_t)(r0 + 8) * ZS + kb + 8];
    }

    float d[5][4];
    #pragma unroll
    for (int nt = 0; nt < 5; nt++)
        #pragma unroll
        for (int i = 0; i < 4; i++) d[nt][i] = 0.f;

    // interleaved: per k-tile kt, compute 2 h tiles (phase A) then consume (phase B)
    #pragma unroll
    for (int kt = 0; kt < 8; kt++) {
        uint32_t hfrag[2][2];
        #pragma unroll
        for (int sub = 0; sub < 2; sub++) {
            int nt = 2 * kt + sub;
            float dd[4] = {0.f, 0.f, 0.f, 0.f};
            #pragma unroll
            for (int zk = 0; zk < 2; zk++) {
                uint2 b = g_Wsf[(nt * 2 + zk) * 32 + lane];
                asm volatile(
                    "mma.sync.aligned.m16n8k16.row.col.f32.f16.f16.f32 "
                    "{%0,%1,%2,%3}, {%4,%5,%6,%7}, {%8,%9}, {%0,%1,%2,%3};"
                    : "+f"(dd[0]), "+f"(dd[1]), "+f"(dd[2]), "+f"(dd[3])
                    : "r"(a[zk][0]), "r"(a[zk][1]), "r"(a[zk][2]), "r"(a[zk][3]),
                      "r"(b.x), "r"(b.y));
            }
            __half2 r0h = __floats2half2_rn(fmaxf(dd[0], 0.f), fmaxf(dd[1], 0.f));
            __half2 r1h = __floats2half2_rn(fmaxf(dd[2], 0.f), fmaxf(dd[3], 0.f));
            hfrag[sub][0] = *(uint32_t*)&r0h;
            hfrag[sub][1] = *(uint32_t*)&r1h;
        }
        #pragma unroll
        for (int nt = 0; nt < 5; nt++) {
            uint2 b = g_W2f[(kt * 5 + nt) * 32 + lane];
            asm volatile(
                "mma.sync.aligned.m16n8k16.row.col.f32.f16.f16.f32 "
                "{%0,%1,%2,%3}, {%4,%5,%6,%7}, {%8,%9}, {%0,%1,%2,%3};"
                : "+f"(d[nt][0]), "+f"(d[nt][1]), "+f"(d[nt][2]), "+f"(d[nt][3])
                : "r"(hfrag[0][0]), "r"(hfrag[0][1]),
                  "r"(hfrag[1][0]), "r"(hfrag[1][1]),
                  "r"(b.x), "r"(b.y));
        }
    }

    int node0 = r0;
    int node1 = r0 + 8;
    if (node0 < NN) {
        #pragma unroll
        for (int nt = 0; nt < 5; nt++)
            g_h2h[(size_t)node0 * C2P + 4 * nt + q] =
                __floats2half2_rn(d[nt][0], d[nt][1]);
    }
    if (node1 < NN) {
        #pragma unroll
        for (int nt = 0; nt < 5; nt++)
            g_h2h[(size_t)node1 * C2P + 4 * nt + q] =
                __floats2half2_rn(d[nt][2], d[nt][3]);
    }
}

// ---------------- layer-2 aggregate: 8 lanes/node (5 active), pairwise HADD2 ----------------
// Also resets g_deg (consume-and-reset invariant for graph replay).
__global__ void k_agg2(float* __restrict__ out)
{
    int gt = blockIdx.x * blockDim.x + threadIdx.x;
    int node = gt >> 3;
    if (node >= NN) return;
    int lane = gt & 7;
    if (lane >= 5) return;            // 5 active lanes x 16B = 80B row (1 line, 128B stride)
    int deg = g_deg[node];
    if (deg > CAP) deg = CAP;
    const int* srcs = g_srcs + (size_t)node * CAP;
    const uint4* gh4 = (const uint4*)g_h2h;    // row stride = 8 uint4
    float a[8];
    #pragma unroll
    for (int i = 0; i < 8; i++) a[i] = 0.f;
    int j = 0;
    for (; j + 3 < deg; j += 4) {
        uint4 q0 = gh4[(size_t)srcs[j]     * 8 + lane];
        uint4 q1 = gh4[(size_t)srcs[j + 1] * 8 + lane];
        uint4 q2 = gh4[(size_t)srcs[j + 2] * 8 + lane];
        uint4 q3 = gh4[(size_t)srcs[j + 3] * 8 + lane];
        const __half2* h0 = (const __half2*)&q0;
        const __half2* h1 = (const __half2*)&q1;
        const __half2* h2 = (const __half2*)&q2;
        const __half2* h3 = (const __half2*)&q3;
        #pragma unroll
        for (int i = 0; i < 4; i++) {
            float2 s = __half22float2(__hadd2(h0[i], h1[i]));
            float2 u = __half22float2(__hadd2(h2[i], h3[i]));
            a[2 * i]     += s.x + u.x;
            a[2 * i + 1] += s.y + u.y;
        }
    }
    for (; j < deg; j++) {
        uint4 q = gh4[(size_t)srcs[j] * 8 + lane];
        const __half2* h = (const __half2*)&q;
        #pragma unroll
        for (int i = 0; i < 4; i++) {
            float2 f = __half22float2(h[i]);
            a[2 * i]     += f.x;
            a[2 * i + 1] += f.y;
        }
    }
    float* orow = out + (size_t)node * C + 8 * lane;
    *(float4*)&orow[0] = make_float4(a[0], a[1], a[2], a[3]);
    *(float4*)&orow[4] = make_float4(a[4], a[5], a[6], a[7]);
    if (lane == 0) g_deg[node] = 0;   // reset for next replay
}

// ---------------- launch ----------------
extern "C" void kernel_launch(void* const* d_in, const int* in_sizes, int n_in,
                              void* d_out, int out_size)
{
    const float* xr = (const float*)d_in[0];
    const float* xu = (const float*)d_in[1];
    const float* xp = (const float*)d_in[2];
    const int*   ei = (const int*)  d_in[3];
    const float* Wr = (const float*)d_in[4];
    const float* br = (const float*)d_in[5];
    const float* Wu = (const float*)d_in[6];
    const float* bu = (const float*)d_in[7];
    const float* Wp = (const float*)d_in[8];
    const float* bp = (const float*)d_in[9];
    const float* W1 = (const float*)d_in[10];
    const float* W2 = (const float*)d_in[11];
    float* out = (float*)d_out;

    const int* src = ei;
    const int* dst = ei + EE;

    k_prepscatter<<<PB_BLOCKS + WSF_BLOCKS + W2F_BLOCKS + SC_BLOCKS, 256>>>(
        Wr, br, Wu, bu, Wp, bp, W1, W2, xr, xu, xp, src, dst);
    k_aggz<<<(NN * 4 + 255) / 256, 256>>>();
    k_mlp<<<(NN + TN - 1) / TN, 256>>>();
    k_agg2<<<(NN * 8 + 255) / 256, 256>>>(out);
}